// round 1
// baseline (speedup 1.0000x reference)
#include <cuda_runtime.h>

#define BATCH 16
#define SEQ   2048
#define DIM   128
#define HID   256
#define KOUT  64
#define TEMP_F 1.0f

// Scratch for Q and K projections (8 MB each) — __device__ globals per harness rules.
__device__ float g_Q[BATCH * SEQ * KOUT];
__device__ float g_K[BATCH * SEQ * KOUT];

// ---------------------------------------------------------------------------
// K1: dual MLP.  Each block: 32 rows of x, one head (blockIdx.y: 0=q, 1=k).
//   h = relu(x @ W1 + b1)   [32 x 256]
//   o =      h @ W2 + b2    [32 x 64]   -> g_Q / g_K
// ---------------------------------------------------------------------------
__global__ void __launch_bounds__(256) mlp_kernel(
    const float* __restrict__ x,
    const float* __restrict__ qW1, const float* __restrict__ qb1,
    const float* __restrict__ qW2, const float* __restrict__ qb2,
    const float* __restrict__ kW1, const float* __restrict__ kb1,
    const float* __restrict__ kW2, const float* __restrict__ kb2)
{
    __shared__ float xs[32][DIM];   // 16 KB
    __shared__ float hs[32][HID];   // 32 KB

    const int tid  = threadIdx.x;
    const int head = blockIdx.y;
    const float* W1 = head ? kW1 : qW1;
    const float* B1 = head ? kb1 : qb1;
    const float* W2 = head ? kW2 : qW2;
    const float* B2 = head ? kb2 : qb2;
    float* outp = head ? g_K : g_Q;
    const int m0 = blockIdx.x * 32;

    // Load x tile: 32 rows x 128 = 1024 float4
    {
        const float4* xg = reinterpret_cast<const float4*>(x + (size_t)m0 * DIM);
        float4* xs4 = reinterpret_cast<float4*>(&xs[0][0]);
#pragma unroll
        for (int s = 0; s < 4; s++)
            xs4[tid + 256 * s] = xg[tid + 256 * s];
    }
    __syncthreads();

    // GEMM1: [32x128] @ [128x256] + b1, ReLU -> hs
    {
        const int tr = tid >> 5;   // 0..7  -> rows tr*4 .. tr*4+3
        const int tc = tid & 31;   // cols tc*8 .. tc*8+7
        float acc[4][8];
#pragma unroll
        for (int j = 0; j < 8; j++) {
            float bv = B1[tc * 8 + j];
#pragma unroll
            for (int i = 0; i < 4; i++) acc[i][j] = bv;
        }
#pragma unroll 4
        for (int k = 0; k < DIM; k++) {
            float a0 = xs[tr * 4 + 0][k];
            float a1 = xs[tr * 4 + 1][k];
            float a2 = xs[tr * 4 + 2][k];
            float a3 = xs[tr * 4 + 3][k];
            float4 blo = *reinterpret_cast<const float4*>(W1 + k * HID + tc * 8);
            float4 bhi = *reinterpret_cast<const float4*>(W1 + k * HID + tc * 8 + 4);
            float bv[8] = {blo.x, blo.y, blo.z, blo.w, bhi.x, bhi.y, bhi.z, bhi.w};
#pragma unroll
            for (int j = 0; j < 8; j++) {
                acc[0][j] = fmaf(a0, bv[j], acc[0][j]);
                acc[1][j] = fmaf(a1, bv[j], acc[1][j]);
                acc[2][j] = fmaf(a2, bv[j], acc[2][j]);
                acc[3][j] = fmaf(a3, bv[j], acc[3][j]);
            }
        }
#pragma unroll
        for (int i = 0; i < 4; i++) {
            float4 v0 = make_float4(fmaxf(acc[i][0], 0.f), fmaxf(acc[i][1], 0.f),
                                    fmaxf(acc[i][2], 0.f), fmaxf(acc[i][3], 0.f));
            float4 v1 = make_float4(fmaxf(acc[i][4], 0.f), fmaxf(acc[i][5], 0.f),
                                    fmaxf(acc[i][6], 0.f), fmaxf(acc[i][7], 0.f));
            *reinterpret_cast<float4*>(&hs[tr * 4 + i][tc * 8])     = v0;
            *reinterpret_cast<float4*>(&hs[tr * 4 + i][tc * 8 + 4]) = v1;
        }
    }
    __syncthreads();

    // GEMM2: [32x256] @ [256x64] + b2 -> out
    {
        const int tr = tid >> 4;   // 0..15 -> rows tr*2, tr*2+1
        const int tc = tid & 15;   // cols tc*4 .. tc*4+3
        float acc[2][4];
#pragma unroll
        for (int j = 0; j < 4; j++) {
            float bv = B2[tc * 4 + j];
            acc[0][j] = bv;
            acc[1][j] = bv;
        }
#pragma unroll 4
        for (int k = 0; k < HID; k++) {
            float a0 = hs[tr * 2 + 0][k];
            float a1 = hs[tr * 2 + 1][k];
            float4 b4 = *reinterpret_cast<const float4*>(W2 + k * KOUT + tc * 4);
            acc[0][0] = fmaf(a0, b4.x, acc[0][0]);
            acc[0][1] = fmaf(a0, b4.y, acc[0][1]);
            acc[0][2] = fmaf(a0, b4.z, acc[0][2]);
            acc[0][3] = fmaf(a0, b4.w, acc[0][3]);
            acc[1][0] = fmaf(a1, b4.x, acc[1][0]);
            acc[1][1] = fmaf(a1, b4.y, acc[1][1]);
            acc[1][2] = fmaf(a1, b4.z, acc[1][2]);
            acc[1][3] = fmaf(a1, b4.w, acc[1][3]);
        }
#pragma unroll
        for (int i = 0; i < 2; i++) {
            float4 v = make_float4(acc[i][0], acc[i][1], acc[i][2], acc[i][3]);
            *reinterpret_cast<float4*>(&outp[(size_t)(m0 + tr * 2 + i) * KOUT + tc * 4]) = v;
        }
    }
}

// ---------------------------------------------------------------------------
// K2: S = Q @ K^T per batch, written raw into d_out (used as scratch).
//   Tile 64x64, full k=64.  Grid (j_tiles=32, i_tiles=32, batch=16).
// ---------------------------------------------------------------------------
__global__ void __launch_bounds__(256) qk_kernel(float* __restrict__ out)
{
    __shared__ float Qs[64][65];   // pad 65 -> conflict-free column reads
    __shared__ float Ks[64][65];

    const int tid = threadIdx.x;
    const int bb  = blockIdx.z;
    const int i0  = blockIdx.y * 64;
    const int j0  = blockIdx.x * 64;

    const float4* Qg = reinterpret_cast<const float4*>(g_Q + ((size_t)bb * SEQ + i0) * KOUT);
    const float4* Kg = reinterpret_cast<const float4*>(g_K + ((size_t)bb * SEQ + j0) * KOUT);

#pragma unroll
    for (int s = 0; s < 4; s++) {
        int f4 = tid + 256 * s;         // 0..1023
        int r  = f4 >> 4;               // row 0..63
        int c4 = f4 & 15;               // float4 within row
        float4 qv = Qg[f4];
        Qs[r][c4 * 4 + 0] = qv.x;
        Qs[r][c4 * 4 + 1] = qv.y;
        Qs[r][c4 * 4 + 2] = qv.z;
        Qs[r][c4 * 4 + 3] = qv.w;
        float4 kv = Kg[f4];
        Ks[r][c4 * 4 + 0] = kv.x;
        Ks[r][c4 * 4 + 1] = kv.y;
        Ks[r][c4 * 4 + 2] = kv.z;
        Ks[r][c4 * 4 + 3] = kv.w;
    }
    __syncthreads();

    const int tr = tid >> 4;   // 0..15 -> rows tr*4..+3
    const int tc = tid & 15;   // cols tc*4..+3
    float acc[4][4];
#pragma unroll
    for (int i = 0; i < 4; i++)
#pragma unroll
        for (int j = 0; j < 4; j++) acc[i][j] = 0.f;

#pragma unroll 8
    for (int k = 0; k < KOUT; k++) {
        float a0 = Qs[tr * 4 + 0][k];
        float a1 = Qs[tr * 4 + 1][k];
        float a2 = Qs[tr * 4 + 2][k];
        float a3 = Qs[tr * 4 + 3][k];
        float b0 = Ks[tc * 4 + 0][k];
        float b1 = Ks[tc * 4 + 1][k];
        float b2 = Ks[tc * 4 + 2][k];
        float b3 = Ks[tc * 4 + 3][k];
        acc[0][0] = fmaf(a0, b0, acc[0][0]); acc[0][1] = fmaf(a0, b1, acc[0][1]);
        acc[0][2] = fmaf(a0, b2, acc[0][2]); acc[0][3] = fmaf(a0, b3, acc[0][3]);
        acc[1][0] = fmaf(a1, b0, acc[1][0]); acc[1][1] = fmaf(a1, b1, acc[1][1]);
        acc[1][2] = fmaf(a1, b2, acc[1][2]); acc[1][3] = fmaf(a1, b3, acc[1][3]);
        acc[2][0] = fmaf(a2, b0, acc[2][0]); acc[2][1] = fmaf(a2, b1, acc[2][1]);
        acc[2][2] = fmaf(a2, b2, acc[2][2]); acc[2][3] = fmaf(a2, b3, acc[2][3]);
        acc[3][0] = fmaf(a3, b0, acc[3][0]); acc[3][1] = fmaf(a3, b1, acc[3][1]);
        acc[3][2] = fmaf(a3, b2, acc[3][2]); acc[3][3] = fmaf(a3, b3, acc[3][3]);
    }

#pragma unroll
    for (int i = 0; i < 4; i++) {
        size_t off = ((size_t)bb * SEQ + (i0 + tr * 4 + i)) * SEQ + (j0 + tc * 4);
        float4 v = make_float4(acc[i][0], acc[i][1], acc[i][2], acc[i][3]);
        *reinterpret_cast<float4*>(out + off) = v;
    }
}

// ---------------------------------------------------------------------------
// K3: per-row fused softmax with max-DIVISION normalization.
//   dist = exp(TEMP * s / rowmax) / sum(exp(TEMP * s / rowmax))
//   One block per row (256 threads, 8 elements/thread), in-place on d_out.
// ---------------------------------------------------------------------------
__global__ void __launch_bounds__(256) softmax_kernel(float* __restrict__ out)
{
    __shared__ float red[8];
    const int tid  = threadIdx.x;
    const int lane = tid & 31;
    const int wid  = tid >> 5;

    float* p = out + (size_t)blockIdx.x * SEQ;
    float4* p4 = reinterpret_cast<float4*>(p);

    float4 v0 = p4[tid];
    float4 v1 = p4[tid + 256];
    float vs[8] = {v0.x, v0.y, v0.z, v0.w, v1.x, v1.y, v1.z, v1.w};

    // --- block max ---
    float mx = vs[0];
#pragma unroll
    for (int i = 1; i < 8; i++) mx = fmaxf(mx, vs[i]);
#pragma unroll
    for (int o = 16; o > 0; o >>= 1) mx = fmaxf(mx, __shfl_xor_sync(0xffffffffu, mx, o));
    if (lane == 0) red[wid] = mx;
    __syncthreads();
    mx = red[0];
#pragma unroll
    for (int w = 1; w < 8; w++) mx = fmaxf(mx, red[w]);

    const float sc = TEMP_F / mx;

    // --- exp + block sum ---
    float e[8];
    float sm = 0.f;
#pragma unroll
    for (int i = 0; i < 8; i++) {
        e[i] = __expf(vs[i] * sc);
        sm += e[i];
    }
#pragma unroll
    for (int o = 16; o > 0; o >>= 1) sm += __shfl_xor_sync(0xffffffffu, sm, o);
    __syncthreads();             // everyone done reading red[] for max
    if (lane == 0) red[wid] = sm;
    __syncthreads();
    float tot = red[0];
#pragma unroll
    for (int w = 1; w < 8; w++) tot += red[w];
    const float inv = 1.f / tot;

    v0 = make_float4(e[0] * inv, e[1] * inv, e[2] * inv, e[3] * inv);
    v1 = make_float4(e[4] * inv, e[5] * inv, e[6] * inv, e[7] * inv);
    p4[tid]       = v0;
    p4[tid + 256] = v1;
}

// ---------------------------------------------------------------------------
extern "C" void kernel_launch(void* const* d_in, const int* in_sizes, int n_in,
                              void* d_out, int out_size)
{
    const float* x   = (const float*)d_in[0];
    const float* qW1 = (const float*)d_in[1];
    const float* qb1 = (const float*)d_in[2];
    const float* qW2 = (const float*)d_in[3];
    const float* qb2 = (const float*)d_in[4];
    const float* kW1 = (const float*)d_in[5];
    const float* kb1 = (const float*)d_in[6];
    const float* kW2 = (const float*)d_in[7];
    const float* kb2 = (const float*)d_in[8];
    float* out = (float*)d_out;

    // K1: MLPs -> g_Q, g_K
    mlp_kernel<<<dim3((BATCH * SEQ) / 32, 2), 256>>>(x, qW1, qb1, qW2, qb2,
                                                     kW1, kb1, kW2, kb2);
    // K2: raw scores into d_out
    qk_kernel<<<dim3(SEQ / 64, SEQ / 64, BATCH), 256>>>(out);
    // K3: in-place max-division softmax
    softmax_kernel<<<BATCH * SEQ, 256>>>(out);
}

// round 3
// speedup vs baseline: 1.3136x; 1.3136x over previous
#include <cuda_runtime.h>
#include <cstdint>

#define BATCH 16
#define SEQ   2048
#define DIM   128
#define HID   256
#define KOUT  64
#define TEMP_F 1.0f

// Scratch for Q and K projections (8 MB each).
__device__ float g_Q[BATCH * SEQ * KOUT];
__device__ float g_K[BATCH * SEQ * KOUT];

// ---------------------------------------------------------------------------
// tf32 helpers
// ---------------------------------------------------------------------------
__device__ __forceinline__ uint32_t f32_to_tf32(float f) {
    uint32_t r;
    asm("cvt.rna.tf32.f32 %0, %1;" : "=r"(r) : "f"(f));
    return r;
}

__device__ __forceinline__ void mma_tf32(float& c0, float& c1, float& c2, float& c3,
                                         uint32_t a0, uint32_t a1, uint32_t a2, uint32_t a3,
                                         uint32_t b0, uint32_t b1) {
    asm volatile(
        "mma.sync.aligned.m16n8k8.row.col.f32.tf32.tf32.f32 "
        "{%0,%1,%2,%3}, {%4,%5,%6,%7}, {%8,%9}, {%0,%1,%2,%3};\n"
        : "+f"(c0), "+f"(c1), "+f"(c2), "+f"(c3)
        : "r"(a0), "r"(a1), "r"(a2), "r"(a3), "r"(b0), "r"(b1));
}

// ---------------------------------------------------------------------------
// K1: dual MLP.  64 rows per block, blockIdx.y: 0=q, 1=k.
//   GEMM1: 8x8 microtile  (thread: 8 rows x {lane*4..+3, 128+lane*4..+3})
//   GEMM2: 4x4 microtile
// Dynamic smem: xs[64][128] (32KB) + hs[64][260] (~65KB)
// ---------------------------------------------------------------------------
#define HS_STRIDE 260
#define MLP_SMEM (64 * DIM * 4 + 64 * HS_STRIDE * 4)

__global__ void __launch_bounds__(256, 2) mlp_kernel(
    const float* __restrict__ x,
    const float* __restrict__ qW1, const float* __restrict__ qb1,
    const float* __restrict__ qW2, const float* __restrict__ qb2,
    const float* __restrict__ kW1, const float* __restrict__ kb1,
    const float* __restrict__ kW2, const float* __restrict__ kb2)
{
    extern __shared__ float sm[];
    float* xs = sm;                 // [64][128]
    float* hs = sm + 64 * DIM;      // [64][HS_STRIDE]

    const int tid  = threadIdx.x;
    const int head = blockIdx.y;
    const float* W1 = head ? kW1 : qW1;
    const float* B1 = head ? kb1 : qb1;
    const float* W2 = head ? kW2 : qW2;
    const float* B2 = head ? kb2 : qb2;
    float* outp = head ? g_K : g_Q;
    const int m0 = blockIdx.x * 64;

    // Load x tile: 64 rows x 32 float4 = 2048 float4, 8 per thread
    {
        const float4* xg = reinterpret_cast<const float4*>(x + (size_t)m0 * DIM);
        float4* xs4 = reinterpret_cast<float4*>(xs);
#pragma unroll
        for (int s = 0; s < 8; s++)
            xs4[tid + 256 * s] = xg[tid + 256 * s];
    }
    __syncthreads();

    // GEMM1: [64x128] @ [128x256] + b1, ReLU -> hs
    {
        const int tr   = tid >> 5;        // warp: rows tr*8 .. tr*8+7
        const int lane = tid & 31;        // cols lane*4..+3 and 128+lane*4..+3
        const int cA = lane * 4;
        const int cB = 128 + lane * 4;

        float acc[8][8];
        {
            float4 bA = *reinterpret_cast<const float4*>(B1 + cA);
            float4 bB = *reinterpret_cast<const float4*>(B1 + cB);
#pragma unroll
            for (int i = 0; i < 8; i++) {
                acc[i][0] = bA.x; acc[i][1] = bA.y; acc[i][2] = bA.z; acc[i][3] = bA.w;
                acc[i][4] = bB.x; acc[i][5] = bB.y; acc[i][6] = bB.z; acc[i][7] = bB.w;
            }
        }
#pragma unroll 4
        for (int k = 0; k < DIM; k++) {
            float4 blo = *reinterpret_cast<const float4*>(W1 + k * HID + cA);
            float4 bhi = *reinterpret_cast<const float4*>(W1 + k * HID + cB);
            float bv[8] = {blo.x, blo.y, blo.z, blo.w, bhi.x, bhi.y, bhi.z, bhi.w};
#pragma unroll
            for (int i = 0; i < 8; i++) {
                float a = xs[(tr * 8 + i) * DIM + k];
#pragma unroll
                for (int j = 0; j < 8; j++)
                    acc[i][j] = fmaf(a, bv[j], acc[i][j]);
            }
        }
#pragma unroll
        for (int i = 0; i < 8; i++) {
            int row = tr * 8 + i;
            float4 v0 = make_float4(fmaxf(acc[i][0], 0.f), fmaxf(acc[i][1], 0.f),
                                    fmaxf(acc[i][2], 0.f), fmaxf(acc[i][3], 0.f));
            float4 v1 = make_float4(fmaxf(acc[i][4], 0.f), fmaxf(acc[i][5], 0.f),
                                    fmaxf(acc[i][6], 0.f), fmaxf(acc[i][7], 0.f));
            *reinterpret_cast<float4*>(&hs[row * HS_STRIDE + cA]) = v0;
            *reinterpret_cast<float4*>(&hs[row * HS_STRIDE + cB]) = v1;
        }
    }
    __syncthreads();

    // GEMM2: [64x256] @ [256x64] + b2 -> out
    {
        const int tr = tid >> 4;   // 0..15 -> rows tr*4..+3
        const int tc = tid & 15;   // cols tc*4..+3
        float acc[4][4];
        {
            float4 b = *reinterpret_cast<const float4*>(B2 + tc * 4);
#pragma unroll
            for (int i = 0; i < 4; i++) {
                acc[i][0] = b.x; acc[i][1] = b.y; acc[i][2] = b.z; acc[i][3] = b.w;
            }
        }
#pragma unroll 4
        for (int k = 0; k < HID; k++) {
            float4 b4 = *reinterpret_cast<const float4*>(W2 + k * KOUT + tc * 4);
#pragma unroll
            for (int i = 0; i < 4; i++) {
                float a = hs[(tr * 4 + i) * HS_STRIDE + k];
                acc[i][0] = fmaf(a, b4.x, acc[i][0]);
                acc[i][1] = fmaf(a, b4.y, acc[i][1]);
                acc[i][2] = fmaf(a, b4.z, acc[i][2]);
                acc[i][3] = fmaf(a, b4.w, acc[i][3]);
            }
        }
#pragma unroll
        for (int i = 0; i < 4; i++) {
            float4 v = make_float4(acc[i][0], acc[i][1], acc[i][2], acc[i][3]);
            *reinterpret_cast<float4*>(&outp[(size_t)(m0 + tr * 4 + i) * KOUT + tc * 4]) = v;
        }
    }
}

// ---------------------------------------------------------------------------
// K2: S = Q @ K^T via tf32 mma.sync.  128x128 block tile, 8 warps (2m x 4n),
// warp tile 64x32.  Q/K tiles tf32-rounded in smem with XOR swizzle.
// Dynamic smem: 2 * 128*64*4 = 64KB.
// ---------------------------------------------------------------------------
#define QK_SMEM (2 * 128 * 64 * 4)

__device__ __forceinline__ int swz(int row, int col) {
    return row * 64 + (col ^ ((row & 7) << 2));
}

__global__ void __launch_bounds__(256, 2) qk_mma_kernel(float* __restrict__ out)
{
    extern __shared__ float sm[];
    float* Qs = sm;              // [128][64] swizzled
    float* Ks = sm + 128 * 64;   // [128][64] swizzled

    const int tid = threadIdx.x;
    const int bb  = blockIdx.z;
    const int i0  = blockIdx.y * 128;
    const int j0  = blockIdx.x * 128;

    // Load + tf32-round Q/K tiles: each tile 128 rows x 16 float4 = 2048 f4.
    {
        const float4* Qg = reinterpret_cast<const float4*>(g_Q + ((size_t)bb * SEQ + i0) * KOUT);
        const float4* Kg = reinterpret_cast<const float4*>(g_K + ((size_t)bb * SEQ + j0) * KOUT);
#pragma unroll
        for (int s = 0; s < 8; s++) {
            int f4  = tid + 256 * s;
            int row = f4 >> 4;
            int c4  = f4 & 15;
            int pc  = (c4 * 4) ^ ((row & 7) << 2);   // swizzled col (4-aligned)
            float4 qv = Qg[f4];
            float4 kv = Kg[f4];
            uint32_t* qd = reinterpret_cast<uint32_t*>(&Qs[row * 64 + pc]);
            uint32_t* kd = reinterpret_cast<uint32_t*>(&Ks[row * 64 + pc]);
            qd[0] = f32_to_tf32(qv.x); qd[1] = f32_to_tf32(qv.y);
            qd[2] = f32_to_tf32(qv.z); qd[3] = f32_to_tf32(qv.w);
            kd[0] = f32_to_tf32(kv.x); kd[1] = f32_to_tf32(kv.y);
            kd[2] = f32_to_tf32(kv.z); kd[3] = f32_to_tf32(kv.w);
        }
    }
    __syncthreads();

    const int warp = tid >> 5;
    const int lane = tid & 31;
    const int wm = warp >> 2;          // 0..1 -> m offset wm*64
    const int wn = warp & 3;           // 0..3 -> n offset wn*32
    const int m0w = wm * 64;
    const int n0w = wn * 32;
    const int g  = lane >> 2;          // 0..7
    const int tg = lane & 3;           // 0..3

    float acc[4][4][4];
#pragma unroll
    for (int mt = 0; mt < 4; mt++)
#pragma unroll
        for (int nt = 0; nt < 4; nt++)
#pragma unroll
            for (int c = 0; c < 4; c++) acc[mt][nt][c] = 0.f;

    const uint32_t* Qu = reinterpret_cast<const uint32_t*>(Qs);
    const uint32_t* Ku = reinterpret_cast<const uint32_t*>(Ks);

#pragma unroll
    for (int ks = 0; ks < 8; ks++) {
        const int k0 = ks * 8;
        uint32_t A[4][4], B[4][2];
#pragma unroll
        for (int mt = 0; mt < 4; mt++) {
            int r = m0w + mt * 16 + g;
            A[mt][0] = Qu[swz(r,     k0 + tg)];
            A[mt][1] = Qu[swz(r + 8, k0 + tg)];
            A[mt][2] = Qu[swz(r,     k0 + tg + 4)];
            A[mt][3] = Qu[swz(r + 8, k0 + tg + 4)];
        }
#pragma unroll
        for (int nt = 0; nt < 4; nt++) {
            int r = n0w + nt * 8 + g;
            B[nt][0] = Ku[swz(r, k0 + tg)];
            B[nt][1] = Ku[swz(r, k0 + tg + 4)];
        }
#pragma unroll
        for (int mt = 0; mt < 4; mt++)
#pragma unroll
            for (int nt = 0; nt < 4; nt++)
                mma_tf32(acc[mt][nt][0], acc[mt][nt][1], acc[mt][nt][2], acc[mt][nt][3],
                         A[mt][0], A[mt][1], A[mt][2], A[mt][3], B[nt][0], B[nt][1]);
    }

    // Epilogue: c0=C[g][2tg] c1=C[g][2tg+1] c2=C[g+8][2tg] c3=C[g+8][2tg+1]
    float* obase = out + (size_t)bb * SEQ * SEQ;
#pragma unroll
    for (int mt = 0; mt < 4; mt++) {
#pragma unroll
        for (int nt = 0; nt < 4; nt++) {
            int r = i0 + m0w + mt * 16 + g;
            int c = j0 + n0w + nt * 8 + 2 * tg;
            *reinterpret_cast<float2*>(&obase[(size_t)r * SEQ + c]) =
                make_float2(acc[mt][nt][0], acc[mt][nt][1]);
            *reinterpret_cast<float2*>(&obase[(size_t)(r + 8) * SEQ + c]) =
                make_float2(acc[mt][nt][2], acc[mt][nt][3]);
        }
    }
}

// ---------------------------------------------------------------------------
// K3: per-row fused softmax with max-DIVISION normalization (in-place).
// ---------------------------------------------------------------------------
__global__ void __launch_bounds__(256) softmax_kernel(float* __restrict__ out)
{
    __shared__ float red[8];
    const int tid  = threadIdx.x;
    const int lane = tid & 31;
    const int wid  = tid >> 5;

    float4* p4 = reinterpret_cast<float4*>(out + (size_t)blockIdx.x * SEQ);

    float4 v0 = p4[tid];
    float4 v1 = p4[tid + 256];
    float vs[8] = {v0.x, v0.y, v0.z, v0.w, v1.x, v1.y, v1.z, v1.w};

    float mx = vs[0];
#pragma unroll
    for (int i = 1; i < 8; i++) mx = fmaxf(mx, vs[i]);
#pragma unroll
    for (int o = 16; o > 0; o >>= 1) mx = fmaxf(mx, __shfl_xor_sync(0xffffffffu, mx, o));
    if (lane == 0) red[wid] = mx;
    __syncthreads();
    mx = red[0];
#pragma unroll
    for (int w = 1; w < 8; w++) mx = fmaxf(mx, red[w]);

    const float sc = TEMP_F / mx;

    float e[8];
    float smm = 0.f;
#pragma unroll
    for (int i = 0; i < 8; i++) {
        e[i] = __expf(vs[i] * sc);
        smm += e[i];
    }
#pragma unroll
    for (int o = 16; o > 0; o >>= 1) smm += __shfl_xor_sync(0xffffffffu, smm, o);
    __syncthreads();
    if (lane == 0) red[wid] = smm;
    __syncthreads();
    float tot = red[0];
#pragma unroll
    for (int w = 1; w < 8; w++) tot += red[w];
    const float inv = 1.f / tot;

    p4[tid]       = make_float4(e[0] * inv, e[1] * inv, e[2] * inv, e[3] * inv);
    p4[tid + 256] = make_float4(e[4] * inv, e[5] * inv, e[6] * inv, e[7] * inv);
}

// ---------------------------------------------------------------------------
extern "C" void kernel_launch(void* const* d_in, const int* in_sizes, int n_in,
                              void* d_out, int out_size)
{
    const float* x   = (const float*)d_in[0];
    const float* qW1 = (const float*)d_in[1];
    const float* qb1 = (const float*)d_in[2];
    const float* qW2 = (const float*)d_in[3];
    const float* qb2 = (const float*)d_in[4];
    const float* kW1 = (const float*)d_in[5];
    const float* kb1 = (const float*)d_in[6];
    const float* kW2 = (const float*)d_in[7];
    const float* kb2 = (const float*)d_in[8];
    float* out = (float*)d_out;

    cudaFuncSetAttribute(mlp_kernel, cudaFuncAttributeMaxDynamicSharedMemorySize, MLP_SMEM);
    cudaFuncSetAttribute(qk_mma_kernel, cudaFuncAttributeMaxDynamicSharedMemorySize, QK_SMEM);

    mlp_kernel<<<dim3((BATCH * SEQ) / 64, 2), 256, MLP_SMEM>>>(
        x, qW1, qb1, qW2, qb2, kW1, kb1, kW2, kb2);

    qk_mma_kernel<<<dim3(SEQ / 128, SEQ / 128, BATCH), 256, QK_SMEM>>>(out);

    softmax_kernel<<<BATCH * SEQ, 256>>>(out);
}

// round 5
// speedup vs baseline: 1.5131x; 1.1519x over previous
#include <cuda_runtime.h>
#include <cuda_bf16.h>
#include <cstdint>

#define BATCH 16
#define SEQ   2048
#define DIM   128
#define HID   256
#define KOUT  64
#define NROWS (BATCH * SEQ)   // 32768

// ---------------------------------------------------------------------------
// Device scratch (hi/lo bf16 split operands)
// ---------------------------------------------------------------------------
__device__ __nv_bfloat16 g_Xhi[NROWS * DIM],  g_Xlo[NROWS * DIM];
__device__ __nv_bfloat16 g_W1T_hi[2 * HID * DIM], g_W1T_lo[2 * HID * DIM];
__device__ __nv_bfloat16 g_W2T_hi[2 * KOUT * HID], g_W2T_lo[2 * KOUT * HID];
__device__ __nv_bfloat16 g_Qhi[NROWS * KOUT], g_Qlo[NROWS * KOUT];
__device__ __nv_bfloat16 g_Khi[NROWS * KOUT], g_Klo[NROWS * KOUT];

// ---------------------------------------------------------------------------
// Helpers
// ---------------------------------------------------------------------------
__device__ __forceinline__ void mma_bf16(float* c, const uint32_t* a, const uint32_t* b) {
    asm volatile(
        "mma.sync.aligned.m16n8k16.row.col.f32.bf16.bf16.f32 "
        "{%0,%1,%2,%3},{%4,%5,%6,%7},{%8,%9},{%0,%1,%2,%3};\n"
        : "+f"(c[0]), "+f"(c[1]), "+f"(c[2]), "+f"(c[3])
        : "r"(a[0]), "r"(a[1]), "r"(a[2]), "r"(a[3]), "r"(b[0]), "r"(b[1]));
}

#define CP_ASYNC16(dst, src) \
    asm volatile("cp.async.cg.shared.global [%0],[%1],16;\n" :: "r"(dst), "l"(src))
#define CP_COMMIT() asm volatile("cp.async.commit_group;\n")
#define CP_WAIT0()  asm volatile("cp.async.wait_group 0;\n")
#define CP_WAIT1()  asm volatile("cp.async.wait_group 1;\n")

__device__ __forceinline__ void split1(float v, __nv_bfloat16& h, __nv_bfloat16& l) {
    h = __float2bfloat16(v);
    l = __float2bfloat16(v - __bfloat162float(h));
}

__device__ __forceinline__ void split_pack(float a, float b, uint32_t& hi, uint32_t& lo) {
    __nv_bfloat16 ha, la, hb, lb;
    split1(a, ha, la);
    split1(b, hb, lb);
    __nv_bfloat162 H = __halves2bfloat162(ha, hb);
    __nv_bfloat162 L = __halves2bfloat162(la, lb);
    hi = *reinterpret_cast<uint32_t*>(&H);
    lo = *reinterpret_cast<uint32_t*>(&L);
}

// ---------------------------------------------------------------------------
// K0: prep — split x, W1^T, W2^T into hi/lo bf16
// ---------------------------------------------------------------------------
__global__ void __launch_bounds__(256) prep_kernel(
    const float* __restrict__ x,
    const float* __restrict__ qW1, const float* __restrict__ kW1,
    const float* __restrict__ qW2, const float* __restrict__ kW2)
{
    int t = blockIdx.x * 256 + threadIdx.x;
    if (t < NROWS * DIM) {
        __nv_bfloat16 h, l;
        split1(x[t], h, l);
        g_Xhi[t] = h; g_Xlo[t] = l;
    }
    if (t < 2 * HID * DIM) {            // W1^T [head][n=256][k=128]
        int head = t / (HID * DIM);
        int r = t % (HID * DIM);
        int n = r / DIM, k = r % DIM;
        float v = (head ? kW1 : qW1)[k * HID + n];
        __nv_bfloat16 h, l;
        split1(v, h, l);
        g_W1T_hi[t] = h; g_W1T_lo[t] = l;
    }
    if (t < 2 * KOUT * HID) {           // W2^T [head][n=64][k=256]
        int head = t / (KOUT * HID);
        int r = t % (KOUT * HID);
        int n = r / HID, k = r % HID;
        float v = (head ? kW2 : qW2)[k * KOUT + n];
        __nv_bfloat16 h, l;
        split1(v, h, l);
        g_W2T_hi[t] = h; g_W2T_lo[t] = l;
    }
}

// ---------------------------------------------------------------------------
// K1: MLP via bf16x3 mma.sync.  CTA = 64 rows, one head.  256 threads.
// smem layout (bytes / words):
//   XS_hi 0       (64 rows x 272B)        XS_lo 17408
//   WB_hi 34816   (128 rows x 272B)       WB_lo 69632   (also W2T 64 x 528B)
//   HS_hi 104448  (64 rows x 528B)        HS_lo 138240  total 172032
// ---------------------------------------------------------------------------
#define XS_HI_W 0
#define XS_LO_W 4352
#define WB_HI_W 8704
#define WB_LO_W 17408
#define HS_HI_W 26112
#define HS_LO_W 34560
#define MLP_SMEM 172032

__global__ void __launch_bounds__(256, 1) mlp_kernel(
    const float* __restrict__ qb1, const float* __restrict__ qb2,
    const float* __restrict__ kb1, const float* __restrict__ kb2)
{
    extern __shared__ uint32_t smw[];
    const uint32_t sbase = (uint32_t)__cvta_generic_to_shared(smw);

    const int tid  = threadIdx.x;
    const int head = blockIdx.y;
    const int m0   = blockIdx.x * 64;
    const float* B1 = head ? kb1 : qb1;
    const float* B2 = head ? kb2 : qb2;

    const int warp = tid >> 5;
    const int lane = tid & 31;
    const int g  = lane >> 2;
    const int tg = lane & 3;

    // ---- X: 64 rows x 256B = 16 chunks/row, hi+lo -> 2048 chunks ----
#pragma unroll
    for (int i = 0; i < 8; i++) {
        int c = tid + 256 * i;
        int ishi = (c < 1024);
        int cc = c & 1023;
        int row = cc >> 4, ch = cc & 15;
        const __nv_bfloat16* src = (ishi ? g_Xhi : g_Xlo) + (size_t)(m0 + row) * DIM + ch * 8;
        CP_ASYNC16(sbase + (ishi ? 0 : 17408) + row * 272 + ch * 16, src);
    }
    // ---- W1 chunk 0: 128 rows x 256B = 16 chunks/row, hi+lo -> 4096 chunks ----
#pragma unroll
    for (int i = 0; i < 16; i++) {
        int c = tid + 256 * i;
        int ishi = (c < 2048);
        int cc = c & 2047;
        int row = cc >> 4, ch = cc & 15;
        const __nv_bfloat16* src = (ishi ? g_W1T_hi : g_W1T_lo)
                                   + (size_t)head * HID * DIM + (size_t)row * DIM + ch * 8;
        CP_ASYNC16(sbase + (ishi ? 34816 : 69632) + row * 272 + ch * 16, src);
    }
    CP_COMMIT();
    CP_WAIT0();
    __syncthreads();

    // ---- GEMM1 over two N-chunks of 128 ----
    const int wm = warp >> 2;       // 0..1 -> m_off = wm*32
    const int wn = warp & 3;        // 0..3 -> n_off(local) = wn*32
    for (int nc = 0; nc < 2; nc++) {
        if (nc == 1) {
            __syncthreads();        // all reads of WB chunk0 done
#pragma unroll
            for (int i = 0; i < 16; i++) {
                int c = tid + 256 * i;
                int ishi = (c < 2048);
                int cc = c & 2047;
                int row = cc >> 4, ch = cc & 15;
                const __nv_bfloat16* src = (ishi ? g_W1T_hi : g_W1T_lo)
                    + (size_t)head * HID * DIM + (size_t)(128 + row) * DIM + ch * 8;
                CP_ASYNC16(sbase + (ishi ? 34816 : 69632) + row * 272 + ch * 16, src);
            }
            CP_COMMIT();
            CP_WAIT0();
            __syncthreads();
        }

        float acc[2][4][4];
#pragma unroll
        for (int nf = 0; nf < 4; nf++) {
            int col = nc * 128 + wn * 32 + nf * 8 + 2 * tg;
            float2 bv = *reinterpret_cast<const float2*>(B1 + col);
#pragma unroll
            for (int mt = 0; mt < 2; mt++) {
                acc[mt][nf][0] = bv.x; acc[mt][nf][1] = bv.y;
                acc[mt][nf][2] = bv.x; acc[mt][nf][3] = bv.y;
            }
        }
#pragma unroll
        for (int ks = 0; ks < 8; ks++) {
            uint32_t ah[2][4], al[2][4];
#pragma unroll
            for (int mt = 0; mt < 2; mt++) {
                int r0 = wm * 32 + mt * 16 + g;
                ah[mt][0] = smw[XS_HI_W + 68 * r0 + 8 * ks + tg];
                ah[mt][1] = smw[XS_HI_W + 68 * (r0 + 8) + 8 * ks + tg];
                ah[mt][2] = smw[XS_HI_W + 68 * r0 + 8 * ks + tg + 4];
                ah[mt][3] = smw[XS_HI_W + 68 * (r0 + 8) + 8 * ks + tg + 4];
                al[mt][0] = smw[XS_LO_W + 68 * r0 + 8 * ks + tg];
                al[mt][1] = smw[XS_LO_W + 68 * (r0 + 8) + 8 * ks + tg];
                al[mt][2] = smw[XS_LO_W + 68 * r0 + 8 * ks + tg + 4];
                al[mt][3] = smw[XS_LO_W + 68 * (r0 + 8) + 8 * ks + tg + 4];
            }
#pragma unroll
            for (int nf = 0; nf < 4; nf++) {
                int nrow = wn * 32 + nf * 8 + g;
                uint32_t bh[2], bl[2];
                bh[0] = smw[WB_HI_W + 68 * nrow + 8 * ks + tg];
                bh[1] = smw[WB_HI_W + 68 * nrow + 8 * ks + tg + 4];
                bl[0] = smw[WB_LO_W + 68 * nrow + 8 * ks + tg];
                bl[1] = smw[WB_LO_W + 68 * nrow + 8 * ks + tg + 4];
#pragma unroll
                for (int mt = 0; mt < 2; mt++) {
                    mma_bf16(acc[mt][nf], ah[mt], bh);
                    mma_bf16(acc[mt][nf], ah[mt], bl);
                    mma_bf16(acc[mt][nf], al[mt], bh);
                }
            }
        }
        // epilogue: relu, split, store to HS
#pragma unroll
        for (int mt = 0; mt < 2; mt++) {
            int r0 = wm * 32 + mt * 16 + g;
#pragma unroll
            for (int nf = 0; nf < 4; nf++) {
                int wc = nc * 64 + wn * 16 + nf * 4 + tg;
                uint32_t hi, lo;
                split_pack(fmaxf(acc[mt][nf][0], 0.f), fmaxf(acc[mt][nf][1], 0.f), hi, lo);
                smw[HS_HI_W + 132 * r0 + wc] = hi;
                smw[HS_LO_W + 132 * r0 + wc] = lo;
                split_pack(fmaxf(acc[mt][nf][2], 0.f), fmaxf(acc[mt][nf][3], 0.f), hi, lo);
                smw[HS_HI_W + 132 * (r0 + 8) + wc] = hi;
                smw[HS_LO_W + 132 * (r0 + 8) + wc] = lo;
            }
        }
    }
    __syncthreads();

    // ---- W2T: 64 rows x 512B = 32 chunks/row, hi+lo -> 4096 chunks ----
#pragma unroll
    for (int i = 0; i < 16; i++) {
        int c = tid + 256 * i;
        int ishi = (c < 2048);
        int cc = c & 2047;
        int row = cc >> 5, ch = cc & 31;
        const __nv_bfloat16* src = (ishi ? g_W2T_hi : g_W2T_lo)
            + (size_t)head * KOUT * HID + (size_t)row * HID + ch * 8;
        CP_ASYNC16(sbase + (ishi ? 34816 : 69632) + row * 528 + ch * 16, src);
    }
    CP_COMMIT();
    CP_WAIT0();
    __syncthreads();

    // ---- GEMM2: [64x256] @ W2T^T -> [64x64] ----
    {
        const int wm2 = warp >> 1;      // m_off = wm2*16
        const int wn2 = warp & 1;       // n_off = wn2*32
        const int m_off = wm2 * 16;
        const int n_off = wn2 * 32;

        float acc[4][4];
#pragma unroll
        for (int nf = 0; nf < 4; nf++) {
            int col = n_off + nf * 8 + 2 * tg;
            float2 bv = *reinterpret_cast<const float2*>(B2 + col);
            acc[nf][0] = bv.x; acc[nf][1] = bv.y;
            acc[nf][2] = bv.x; acc[nf][3] = bv.y;
        }
#pragma unroll
        for (int ks = 0; ks < 16; ks++) {
            uint32_t ah[4], al[4];
            int r0 = m_off + g;
            ah[0] = smw[HS_HI_W + 132 * r0 + 8 * ks + tg];
            ah[1] = smw[HS_HI_W + 132 * (r0 + 8) + 8 * ks + tg];
            ah[2] = smw[HS_HI_W + 132 * r0 + 8 * ks + tg + 4];
            ah[3] = smw[HS_HI_W + 132 * (r0 + 8) + 8 * ks + tg + 4];
            al[0] = smw[HS_LO_W + 132 * r0 + 8 * ks + tg];
            al[1] = smw[HS_LO_W + 132 * (r0 + 8) + 8 * ks + tg];
            al[2] = smw[HS_LO_W + 132 * r0 + 8 * ks + tg + 4];
            al[3] = smw[HS_LO_W + 132 * (r0 + 8) + 8 * ks + tg + 4];
#pragma unroll
            for (int nf = 0; nf < 4; nf++) {
                int nrow = n_off + nf * 8 + g;
                uint32_t bh[2], bl[2];
                bh[0] = smw[WB_HI_W + 132 * nrow + 8 * ks + tg];
                bh[1] = smw[WB_HI_W + 132 * nrow + 8 * ks + tg + 4];
                bl[0] = smw[WB_LO_W + 132 * nrow + 8 * ks + tg];
                bl[1] = smw[WB_LO_W + 132 * nrow + 8 * ks + tg + 4];
                mma_bf16(acc[nf], ah, bh);
                mma_bf16(acc[nf], ah, bl);
                mma_bf16(acc[nf], al, bh);
            }
        }
        // epilogue: split -> g_Q/g_K hi+lo
        __nv_bfloat16* Ohi = head ? g_Khi : g_Qhi;
        __nv_bfloat16* Olo = head ? g_Klo : g_Qlo;
#pragma unroll
        for (int nf = 0; nf < 4; nf++) {
            int col = n_off + nf * 8 + 2 * tg;
            int row0 = m0 + m_off + g;
            uint32_t hi, lo;
            split_pack(acc[nf][0], acc[nf][1], hi, lo);
            *reinterpret_cast<uint32_t*>(&Ohi[(size_t)row0 * KOUT + col]) = hi;
            *reinterpret_cast<uint32_t*>(&Olo[(size_t)row0 * KOUT + col]) = lo;
            split_pack(acc[nf][2], acc[nf][3], hi, lo);
            *reinterpret_cast<uint32_t*>(&Ohi[(size_t)(row0 + 8) * KOUT + col]) = hi;
            *reinterpret_cast<uint32_t*>(&Olo[(size_t)(row0 + 8) * KOUT + col]) = lo;
        }
    }
}

// ---------------------------------------------------------------------------
// K2: fused QK^T + max-division softmax.  CTA = 16 rows x full 2048 cols.
// 512 threads (16 warps: each an 8-col slice per j-tile; then 1 row each).
// smem: S[16][2056] f32 (131584) | Qhi/Qlo [16][72] bf16 | K 2-stage hi/lo
// ---------------------------------------------------------------------------
#define S_STRIDE_W 2056
#define QH_W 32896
#define QL_W 33472
#define KST_B(s) (136192 + (s) * 36864)
#define KH_W(s)  (34048 + (s) * 9216)
#define KL_W(s)  (34048 + (s) * 9216 + 4608)
#define QKS_SMEM 209920

__global__ void __launch_bounds__(512, 1) qks_kernel(float* __restrict__ out)
{
    extern __shared__ uint32_t smw[];
    float* Sf = reinterpret_cast<float*>(smw);
    __shared__ float red[16][16];
    const uint32_t sbase = (uint32_t)__cvta_generic_to_shared(smw);

    const int tid  = threadIdx.x;
    const int warp = tid >> 5;
    const int lane = tid & 31;
    const int g  = lane >> 2;
    const int tg = lane & 3;
    const int b  = blockIdx.y;
    const int i0 = blockIdx.x * 16;

    // Q: 16 rows x 128B = 8 chunks/row, hi+lo -> 256 chunks
    if (tid < 256) {
        int c = tid;
        int ishi = (c < 128);
        int cc = c & 127;
        int row = cc >> 3, ch = cc & 7;
        const __nv_bfloat16* src = (ishi ? g_Qhi : g_Qlo)
            + ((size_t)(b * SEQ + i0 + row)) * KOUT + ch * 8;
        CP_ASYNC16(sbase + (ishi ? 131584 : 133888) + row * 144 + ch * 16, src);
    }
    // K stage 0: 128 rows x 128B = 8 chunks/row, hi+lo -> 2048 chunks
#pragma unroll
    for (int i = 0; i < 4; i++) {
        int c = tid + 512 * i;
        int ishi = (c < 1024);
        int cc = c & 1023;
        int row = cc >> 3, ch = cc & 7;
        const __nv_bfloat16* src = (ishi ? g_Khi : g_Klo)
            + ((size_t)(b * SEQ + row)) * KOUT + ch * 8;
        CP_ASYNC16(sbase + KST_B(0) + (ishi ? 0 : 18432) + row * 144 + ch * 16, src);
    }
    CP_COMMIT();
    CP_WAIT0();
    __syncthreads();

    // A fragments (Q) live in registers for the whole kernel
    uint32_t qh[4][4], ql[4][4];
#pragma unroll
    for (int ks = 0; ks < 4; ks++) {
        qh[ks][0] = smw[QH_W + 36 * g + 8 * ks + tg];
        qh[ks][1] = smw[QH_W + 36 * (g + 8) + 8 * ks + tg];
        qh[ks][2] = smw[QH_W + 36 * g + 8 * ks + tg + 4];
        qh[ks][3] = smw[QH_W + 36 * (g + 8) + 8 * ks + tg + 4];
        ql[ks][0] = smw[QL_W + 36 * g + 8 * ks + tg];
        ql[ks][1] = smw[QL_W + 36 * (g + 8) + 8 * ks + tg];
        ql[ks][2] = smw[QL_W + 36 * g + 8 * ks + tg + 4];
        ql[ks][3] = smw[QL_W + 36 * (g + 8) + 8 * ks + tg + 4];
    }

    const float NEG_INF = __int_as_float(0xff800000);
    float mx0 = NEG_INF, mx1 = NEG_INF;

    for (int jt = 0; jt < 16; jt++) {
        if (jt < 15) {
            int st = (jt + 1) & 1;
#pragma unroll
            for (int i = 0; i < 4; i++) {
                int c = tid + 512 * i;
                int ishi = (c < 1024);
                int cc = c & 1023;
                int row = cc >> 3, ch = cc & 7;
                const __nv_bfloat16* src = (ishi ? g_Khi : g_Klo)
                    + ((size_t)(b * SEQ + (jt + 1) * 128 + row)) * KOUT + ch * 8;
                CP_ASYNC16(sbase + KST_B(st) + (ishi ? 0 : 18432) + row * 144 + ch * 16, src);
            }
            CP_COMMIT();
            CP_WAIT1();
        } else {
            CP_WAIT0();
        }
        __syncthreads();

        const int st = jt & 1;
        const int khw = KH_W(st), klw = KL_W(st);
        const int nrow = warp * 8 + g;
        float acc[4] = {0.f, 0.f, 0.f, 0.f};
#pragma unroll
        for (int ks = 0; ks < 4; ks++) {
            uint32_t bh[2], bl[2];
            bh[0] = smw[khw + 36 * nrow + 8 * ks + tg];
            bh[1] = smw[khw + 36 * nrow + 8 * ks + tg + 4];
            bl[0] = smw[klw + 36 * nrow + 8 * ks + tg];
            bl[1] = smw[klw + 36 * nrow + 8 * ks + tg + 4];
            mma_bf16(acc, qh[ks], bh);
            mma_bf16(acc, qh[ks], bl);
            mma_bf16(acc, ql[ks], bh);
        }
        // store to S, track running row max
        const int col = jt * 128 + warp * 8 + 2 * tg;
        *reinterpret_cast<float2*>(&Sf[S_STRIDE_W * g + col]) = make_float2(acc[0], acc[1]);
        *reinterpret_cast<float2*>(&Sf[S_STRIDE_W * (g + 8) + col]) = make_float2(acc[2], acc[3]);
        mx0 = fmaxf(mx0, fmaxf(acc[0], acc[1]));
        mx1 = fmaxf(mx1, fmaxf(acc[2], acc[3]));
        __syncthreads();
    }

    // cross-quad then cross-warp max reduce
    mx0 = fmaxf(mx0, __shfl_xor_sync(0xffffffffu, mx0, 1));
    mx0 = fmaxf(mx0, __shfl_xor_sync(0xffffffffu, mx0, 2));
    mx1 = fmaxf(mx1, __shfl_xor_sync(0xffffffffu, mx1, 1));
    mx1 = fmaxf(mx1, __shfl_xor_sync(0xffffffffu, mx1, 2));
    if (tg == 0) {
        red[warp][g]     = mx0;
        red[warp][g + 8] = mx1;
    }
    __syncthreads();

    // warp w handles row w
    const int r = warp;
    float mx = red[0][r];
#pragma unroll
    for (int w = 1; w < 16; w++) mx = fmaxf(mx, red[w][r]);
    const float sc = 1.0f / mx;    // TEMP = 1

    float4* Srow = reinterpret_cast<float4*>(Sf + (size_t)S_STRIDE_W * r);
    float sum = 0.f;
#pragma unroll
    for (int i = 0; i < 16; i++) {
        float4 v = Srow[lane + 32 * i];
        v.x = __expf(v.x * sc);
        v.y = __expf(v.y * sc);
        v.z = __expf(v.z * sc);
        v.w = __expf(v.w * sc);
        sum += (v.x + v.y) + (v.z + v.w);
        Srow[lane + 32 * i] = v;
    }
#pragma unroll
    for (int o = 16; o > 0; o >>= 1) sum += __shfl_xor_sync(0xffffffffu, sum, o);
    const float inv = 1.0f / sum;

    float4* Orow = reinterpret_cast<float4*>(out + ((size_t)(b * SEQ + i0 + r)) * SEQ);
#pragma unroll
    for (int i = 0; i < 16; i++) {
        float4 v = Srow[lane + 32 * i];
        Orow[lane + 32 * i] = make_float4(v.x * inv, v.y * inv, v.z * inv, v.w * inv);
    }
}

// ---------------------------------------------------------------------------
extern "C" void kernel_launch(void* const* d_in, const int* in_sizes, int n_in,
                              void* d_out, int out_size)
{
    const float* x   = (const float*)d_in[0];
    const float* qW1 = (const float*)d_in[1];
    const float* qb1 = (const float*)d_in[2];
    const float* qW2 = (const float*)d_in[3];
    const float* qb2 = (const float*)d_in[4];
    const float* kW1 = (const float*)d_in[5];
    const float* kb1 = (const float*)d_in[6];
    const float* kW2 = (const float*)d_in[7];
    const float* kb2 = (const float*)d_in[8];
    float* out = (float*)d_out;

    cudaFuncSetAttribute(mlp_kernel, cudaFuncAttributeMaxDynamicSharedMemorySize, MLP_SMEM);
    cudaFuncSetAttribute(qks_kernel, cudaFuncAttributeMaxDynamicSharedMemorySize, QKS_SMEM);

    prep_kernel<<<(NROWS * DIM) / 256, 256>>>(x, qW1, kW1, qW2, kW2);
    mlp_kernel<<<dim3(512, 2), 256, MLP_SMEM>>>(qb1, qb2, kb1, kb2);
    qks_kernel<<<dim3(SEQ / 16, BATCH), 512, QKS_SMEM>>>(out);
}

// round 6
// speedup vs baseline: 2.4224x; 1.6009x over previous
#include <cuda_runtime.h>
#include <cuda_bf16.h>
#include <cstdint>

#define BATCH 16
#define SEQ   2048
#define DIM   128
#define HID   256
#define KOUT  64
#define NROWS (BATCH * SEQ)   // 32768

// ---------------------------------------------------------------------------
// Device scratch: hi/lo bf16 split weights + Q/K projections
// ---------------------------------------------------------------------------
__device__ __nv_bfloat16 g_W1T_hi[2 * HID * DIM], g_W1T_lo[2 * HID * DIM];
__device__ __nv_bfloat16 g_W2T_hi[2 * KOUT * HID], g_W2T_lo[2 * KOUT * HID];
__device__ __nv_bfloat16 g_Qhi[NROWS * KOUT], g_Qlo[NROWS * KOUT];
__device__ __nv_bfloat16 g_Khi[NROWS * KOUT], g_Klo[NROWS * KOUT];

// ---------------------------------------------------------------------------
// Helpers
// ---------------------------------------------------------------------------
__device__ __forceinline__ void mma_bf16(float* c, const uint32_t* a, const uint32_t* b) {
    asm volatile(
        "mma.sync.aligned.m16n8k16.row.col.f32.bf16.bf16.f32 "
        "{%0,%1,%2,%3},{%4,%5,%6,%7},{%8,%9},{%0,%1,%2,%3};\n"
        : "+f"(c[0]), "+f"(c[1]), "+f"(c[2]), "+f"(c[3])
        : "r"(a[0]), "r"(a[1]), "r"(a[2]), "r"(a[3]), "r"(b[0]), "r"(b[1]));
}

#define CP_ASYNC16(dst, src) \
    asm volatile("cp.async.cg.shared.global [%0],[%1],16;\n" :: "r"(dst), "l"(src))
#define CP_COMMIT() asm volatile("cp.async.commit_group;\n")
#define CP_WAIT0()  asm volatile("cp.async.wait_group 0;\n")
#define CP_WAIT1()  asm volatile("cp.async.wait_group 1;\n")
#define CP_WAIT2()  asm volatile("cp.async.wait_group 2;\n")

__device__ __forceinline__ void split1(float v, __nv_bfloat16& h, __nv_bfloat16& l) {
    h = __float2bfloat16(v);
    l = __float2bfloat16(v - __bfloat162float(h));
}

__device__ __forceinline__ void split_pack(float a, float b, uint32_t& hi, uint32_t& lo) {
    __nv_bfloat16 ha, la, hb, lb;
    split1(a, ha, la);
    split1(b, hb, lb);
    __nv_bfloat162 H = __halves2bfloat162(ha, hb);
    __nv_bfloat162 L = __halves2bfloat162(la, lb);
    hi = *reinterpret_cast<uint32_t*>(&H);
    lo = *reinterpret_cast<uint32_t*>(&L);
}

// ---------------------------------------------------------------------------
// K0: prep — split W1^T, W2^T into hi/lo bf16 (weights only; x split is in mlp)
// ---------------------------------------------------------------------------
__global__ void __launch_bounds__(256) prep_kernel(
    const float* __restrict__ qW1, const float* __restrict__ kW1,
    const float* __restrict__ qW2, const float* __restrict__ kW2)
{
    int t = blockIdx.x * 256 + threadIdx.x;
    if (t < 2 * HID * DIM) {            // W1^T [head][n=256][k=128]
        int head = t / (HID * DIM);
        int r = t % (HID * DIM);
        int n = r / DIM, k = r % DIM;
        float v = (head ? kW1 : qW1)[k * HID + n];
        __nv_bfloat16 h, l;
        split1(v, h, l);
        g_W1T_hi[t] = h; g_W1T_lo[t] = l;
    }
    if (t < 2 * KOUT * HID) {           // W2^T [head][n=64][k=256]
        int head = t / (KOUT * HID);
        int r = t % (KOUT * HID);
        int n = r / HID, k = r % HID;
        float v = (head ? kW2 : qW2)[k * HID + n - (k * HID + n) + k * KOUT + n]; // = [k*KOUT+n]
        v = (head ? kW2 : qW2)[k * KOUT + n];
        __nv_bfloat16 h, l;
        split1(v, h, l);
        g_W2T_hi[t] = h; g_W2T_lo[t] = l;
    }
}

// ---------------------------------------------------------------------------
// K1: MLP via bf16x3 mma.sync.  CTA = 64 rows, one head.  256 threads.
// smem (32-bit words):
//   XS hi 0 / lo 4352          (64 rows x 68 w)            8704 w
//   W1 ring R(s)=8704+s*8704   3 stages (hi 64x68, lo +4352)
//     R1 also reused for W2hi (64x132w), R2 for W2lo
//   HS hi 34816 / lo 43264     (64 rows x 132 w)           end 51712 w = 206848 B
// ---------------------------------------------------------------------------
#define MXS_HI 0
#define MXS_LO 4352
#define MR(s)  (8704 + (s) * 8704)
#define MHS_HI 34816
#define MHS_LO 43264
#define MLP_SMEM 206848

__global__ void __launch_bounds__(256, 1) mlp_kernel(
    const float* __restrict__ x,
    const float* __restrict__ qb1, const float* __restrict__ qb2,
    const float* __restrict__ kb1, const float* __restrict__ kb2)
{
    extern __shared__ uint32_t smw[];
    const uint32_t sbase = (uint32_t)__cvta_generic_to_shared(smw);

    const int tid  = threadIdx.x;
    const int head = blockIdx.y;
    const int m0   = blockIdx.x * 64;
    const float* B1 = head ? kb1 : qb1;
    const float* B2 = head ? kb2 : qb2;

    const int warp = tid >> 5;
    const int lane = tid & 31;
    const int g  = lane >> 2;
    const int tg = lane & 3;

    // ---- issue W1 chunks 0..2 into ring stages 0..2 (one group each) ----
#pragma unroll
    for (int s = 0; s < 3; s++) {
#pragma unroll
        for (int i = 0; i < 8; i++) {       // 2048 chunks (hi+lo)
            int c = tid + 256 * i;
            int ishi = (c < 1024);
            int cc = c & 1023;
            int row = cc >> 4, ch = cc & 15;
            const __nv_bfloat16* src = (ishi ? g_W1T_hi : g_W1T_lo)
                + (size_t)head * HID * DIM + (size_t)(s * 64 + row) * DIM + ch * 8;
            CP_ASYNC16(sbase + MR(s) * 4 + (ishi ? 0 : 17408) + row * 272 + ch * 16, src);
        }
        CP_COMMIT();
    }

    // ---- X: LDG f32, split, STS (overlaps with cp.async) ----
    {
        int row = tid >> 2;
        int c0  = (tid & 3) * 32;
        const float4* xr = reinterpret_cast<const float4*>(x + (size_t)(m0 + row) * DIM + c0);
#pragma unroll
        for (int i = 0; i < 8; i++) {
            float4 v = xr[i];
            uint32_t h0, l0, h1, l1;
            split_pack(v.x, v.y, h0, l0);
            split_pack(v.z, v.w, h1, l1);
            int wc = (c0 >> 1) + i * 2;
            smw[MXS_HI + row * 68 + wc]     = h0;
            smw[MXS_HI + row * 68 + wc + 1] = h1;
            smw[MXS_LO + row * 68 + wc]     = l0;
            smw[MXS_LO + row * 68 + wc + 1] = l1;
        }
    }

    // ---- GEMM1: 4 n-chunks of 64, ring-3 pipelined ----
    const int wm = warp >> 1;     // 0..3 -> rows wm*16
    const int wn = warp & 1;      // 0..1 -> cols wn*32 (within chunk)
    const int r0 = wm * 16 + g;

#pragma unroll
    for (int nc = 0; nc < 4; nc++) {
        if (nc == 0) CP_WAIT2(); else CP_WAIT1();
        __syncthreads();
        // issue follow-ups (safe: barrier above proves prior consumers done)
        if (nc == 1) {           // W1 chunk 3 -> R0
#pragma unroll
            for (int i = 0; i < 8; i++) {
                int c = tid + 256 * i;
                int ishi = (c < 1024);
                int cc = c & 1023;
                int row = cc >> 4, ch = cc & 15;
                const __nv_bfloat16* src = (ishi ? g_W1T_hi : g_W1T_lo)
                    + (size_t)head * HID * DIM + (size_t)(192 + row) * DIM + ch * 8;
                CP_ASYNC16(sbase + MR(0) * 4 + (ishi ? 0 : 17408) + row * 272 + ch * 16, src);
            }
            CP_COMMIT();
        } else if (nc == 2) {    // W2 hi -> R1
#pragma unroll
            for (int i = 0; i < 8; i++) {
                int c = tid + 256 * i;
                int row = c >> 5, ch = c & 31;
                const __nv_bfloat16* src = g_W2T_hi
                    + (size_t)head * KOUT * HID + (size_t)row * HID + ch * 8;
                CP_ASYNC16(sbase + MR(1) * 4 + row * 528 + ch * 16, src);
            }
            CP_COMMIT();
        } else if (nc == 3) {    // W2 lo -> R2
#pragma unroll
            for (int i = 0; i < 8; i++) {
                int c = tid + 256 * i;
                int row = c >> 5, ch = c & 31;
                const __nv_bfloat16* src = g_W2T_lo
                    + (size_t)head * KOUT * HID + (size_t)row * HID + ch * 8;
                CP_ASYNC16(sbase + MR(2) * 4 + row * 528 + ch * 16, src);
            }
            CP_COMMIT();
        }

        const int sw = MR(nc % 3);
        float acc[4][4];
#pragma unroll
        for (int nf = 0; nf < 4; nf++) {
            int col = nc * 64 + wn * 32 + nf * 8 + 2 * tg;
            float2 bv = *reinterpret_cast<const float2*>(B1 + col);
            acc[nf][0] = bv.x; acc[nf][1] = bv.y;
            acc[nf][2] = bv.x; acc[nf][3] = bv.y;
        }
#pragma unroll
        for (int ks = 0; ks < 8; ks++) {
            uint32_t ah[4], al[4];
            ah[0] = smw[MXS_HI + 68 * r0 + 8 * ks + tg];
            ah[1] = smw[MXS_HI + 68 * (r0 + 8) + 8 * ks + tg];
            ah[2] = smw[MXS_HI + 68 * r0 + 8 * ks + tg + 4];
            ah[3] = smw[MXS_HI + 68 * (r0 + 8) + 8 * ks + tg + 4];
            al[0] = smw[MXS_LO + 68 * r0 + 8 * ks + tg];
            al[1] = smw[MXS_LO + 68 * (r0 + 8) + 8 * ks + tg];
            al[2] = smw[MXS_LO + 68 * r0 + 8 * ks + tg + 4];
            al[3] = smw[MXS_LO + 68 * (r0 + 8) + 8 * ks + tg + 4];
#pragma unroll
            for (int nf = 0; nf < 4; nf++) {
                int nrow = wn * 32 + nf * 8 + g;
                uint32_t bh[2], bl[2];
                bh[0] = smw[sw + 68 * nrow + 8 * ks + tg];
                bh[1] = smw[sw + 68 * nrow + 8 * ks + tg + 4];
                bl[0] = smw[sw + 4352 + 68 * nrow + 8 * ks + tg];
                bl[1] = smw[sw + 4352 + 68 * nrow + 8 * ks + tg + 4];
                mma_bf16(acc[nf], ah, bh);
                mma_bf16(acc[nf], ah, bl);
                mma_bf16(acc[nf], al, bh);
            }
        }
        // epilogue: relu + split -> HS
#pragma unroll
        for (int nf = 0; nf < 4; nf++) {
            int hw = nc * 32 + wn * 16 + nf * 4 + tg;
            uint32_t hi, lo;
            split_pack(fmaxf(acc[nf][0], 0.f), fmaxf(acc[nf][1], 0.f), hi, lo);
            smw[MHS_HI + 132 * r0 + hw] = hi;
            smw[MHS_LO + 132 * r0 + hw] = lo;
            split_pack(fmaxf(acc[nf][2], 0.f), fmaxf(acc[nf][3], 0.f), hi, lo);
            smw[MHS_HI + 132 * (r0 + 8) + hw] = hi;
            smw[MHS_LO + 132 * (r0 + 8) + hw] = lo;
        }
    }

    CP_WAIT0();      // W2 hi+lo landed
    __syncthreads(); // HS complete

    // ---- GEMM2: [64x256] @ W2T^T -> [64x64] ----
    {
        const int wm2 = warp >> 1;
        const int wn2 = warp & 1;
        const int ra = wm2 * 16 + g;
        const int n_off = wn2 * 32;

        float acc[4][4];
#pragma unroll
        for (int nf = 0; nf < 4; nf++) {
            int col = n_off + nf * 8 + 2 * tg;
            float2 bv = *reinterpret_cast<const float2*>(B2 + col);
            acc[nf][0] = bv.x; acc[nf][1] = bv.y;
            acc[nf][2] = bv.x; acc[nf][3] = bv.y;
        }
#pragma unroll
        for (int ks = 0; ks < 16; ks++) {
            uint32_t ah[4], al[4];
            ah[0] = smw[MHS_HI + 132 * ra + 8 * ks + tg];
            ah[1] = smw[MHS_HI + 132 * (ra + 8) + 8 * ks + tg];
            ah[2] = smw[MHS_HI + 132 * ra + 8 * ks + tg + 4];
            ah[3] = smw[MHS_HI + 132 * (ra + 8) + 8 * ks + tg + 4];
            al[0] = smw[MHS_LO + 132 * ra + 8 * ks + tg];
            al[1] = smw[MHS_LO + 132 * (ra + 8) + 8 * ks + tg];
            al[2] = smw[MHS_LO + 132 * ra + 8 * ks + tg + 4];
            al[3] = smw[MHS_LO + 132 * (ra + 8) + 8 * ks + tg + 4];
#pragma unroll
            for (int nf = 0; nf < 4; nf++) {
                int nrow = n_off + nf * 8 + g;
                uint32_t bh[2], bl[2];
                bh[0] = smw[MR(1) + 132 * nrow + 8 * ks + tg];
                bh[1] = smw[MR(1) + 132 * nrow + 8 * ks + tg + 4];
                bl[0] = smw[MR(2) + 132 * nrow + 8 * ks + tg];
                bl[1] = smw[MR(2) + 132 * nrow + 8 * ks + tg + 4];
                mma_bf16(acc[nf], ah, bh);
                mma_bf16(acc[nf], ah, bl);
                mma_bf16(acc[nf], al, bh);
            }
        }
        __nv_bfloat16* Ohi = head ? g_Khi : g_Qhi;
        __nv_bfloat16* Olo = head ? g_Klo : g_Qlo;
#pragma unroll
        for (int nf = 0; nf < 4; nf++) {
            int col = n_off + nf * 8 + 2 * tg;
            int row0 = m0 + wm2 * 16 + g;
            uint32_t hi, lo;
            split_pack(acc[nf][0], acc[nf][1], hi, lo);
            *reinterpret_cast<uint32_t*>(&Ohi[(size_t)row0 * KOUT + col]) = hi;
            *reinterpret_cast<uint32_t*>(&Olo[(size_t)row0 * KOUT + col]) = lo;
            split_pack(acc[nf][2], acc[nf][3], hi, lo);
            *reinterpret_cast<uint32_t*>(&Ohi[(size_t)(row0 + 8) * KOUT + col]) = hi;
            *reinterpret_cast<uint32_t*>(&Olo[(size_t)(row0 + 8) * KOUT + col]) = lo;
        }
    }
}

// ---------------------------------------------------------------------------
// K2: fused QK^T + max-division softmax.  CTA = 16 rows x 2048 cols, 512 thr.
// S lives in registers (64 f32/thread).  K streamed through a 4-stage ring.
// smem (words): Q hi 0 / lo 576 (16x36); K stage s at 1152+s*9216 (hi, lo +4608)
// total = 4608 + 4*36864 = 152064 B
// ---------------------------------------------------------------------------
#define QKW(s) (1152 + (s) * 9216)
#define QKS_SMEM 152064

__global__ void __launch_bounds__(512, 1) qks_kernel(float* __restrict__ out)
{
    extern __shared__ uint32_t smw[];
    __shared__ float red[16][16];
    const uint32_t sbase = (uint32_t)__cvta_generic_to_shared(smw);

    const int tid  = threadIdx.x;
    const int warp = tid >> 5;
    const int lane = tid & 31;
    const int g  = lane >> 2;
    const int tg = lane & 3;
    const int b  = blockIdx.y;
    const int i0 = blockIdx.x * 16;

#define K_LOAD(slot, jtile)                                                        \
    {                                                                              \
        _Pragma("unroll")                                                          \
        for (int i = 0; i < 4; i++) {                                              \
            int c = tid + 512 * i;                                                 \
            int ishi = (c < 1024);                                                 \
            int cc = c & 1023;                                                     \
            int row = cc >> 3, ch = cc & 7;                                        \
            const __nv_bfloat16* src = (ishi ? g_Khi : g_Klo)                      \
                + ((size_t)(b * SEQ + (jtile) * 128 + row)) * KOUT + ch * 8;       \
            CP_ASYNC16(sbase + QKW(slot) * 4 + (ishi ? 0 : 18432) + row * 144 + ch * 16, src); \
        }                                                                          \
    }

    // group 0: Q + K tile 0
    if (tid < 256) {
        int c = tid;
        int ishi = (c < 128);
        int cc = c & 127;
        int row = cc >> 3, ch = cc & 7;
        const __nv_bfloat16* src = (ishi ? g_Qhi : g_Qlo)
            + ((size_t)(b * SEQ + i0 + row)) * KOUT + ch * 8;
        CP_ASYNC16(sbase + (ishi ? 0 : 2304) + row * 144 + ch * 16, src);
    }
    K_LOAD(0, 0); CP_COMMIT();
    K_LOAD(1, 1); CP_COMMIT();
    K_LOAD(2, 2); CP_COMMIT();

    uint32_t qh[4][4], ql[4][4];
    float S[16][4];
    const float NEG_INF = __int_as_float(0xff800000);
    float mx0 = NEG_INF, mx1 = NEG_INF;
    const int nrow = warp * 8 + g;

#pragma unroll
    for (int jt = 0; jt < 16; jt++) {
        if (jt <= 13) CP_WAIT2(); else if (jt == 14) CP_WAIT1(); else CP_WAIT0();
        __syncthreads();

        if (jt == 0) {
            // Q fragments, kept in registers for the whole kernel
#pragma unroll
            for (int ks = 0; ks < 4; ks++) {
                qh[ks][0] = smw[36 * g + 8 * ks + tg];
                qh[ks][1] = smw[36 * (g + 8) + 8 * ks + tg];
                qh[ks][2] = smw[36 * g + 8 * ks + tg + 4];
                qh[ks][3] = smw[36 * (g + 8) + 8 * ks + tg + 4];
                ql[ks][0] = smw[576 + 36 * g + 8 * ks + tg];
                ql[ks][1] = smw[576 + 36 * (g + 8) + 8 * ks + tg];
                ql[ks][2] = smw[576 + 36 * g + 8 * ks + tg + 4];
                ql[ks][3] = smw[576 + 36 * (g + 8) + 8 * ks + tg + 4];
            }
        }
        if (jt + 3 <= 15) {     // prefetch K tile jt+3 into slot (jt+3)%4
            K_LOAD((jt + 3) & 3, jt + 3);
            CP_COMMIT();
        }

        const int khw = QKW(jt & 3);
        const int klw = khw + 4608;
        float acc[4] = {0.f, 0.f, 0.f, 0.f};
#pragma unroll
        for (int ks = 0; ks < 4; ks++) {
            uint32_t bh[2], bl[2];
            bh[0] = smw[khw + 36 * nrow + 8 * ks + tg];
            bh[1] = smw[khw + 36 * nrow + 8 * ks + tg + 4];
            bl[0] = smw[klw + 36 * nrow + 8 * ks + tg];
            bl[1] = smw[klw + 36 * nrow + 8 * ks + tg + 4];
            mma_bf16(acc, qh[ks], bh);
            mma_bf16(acc, qh[ks], bl);
            mma_bf16(acc, ql[ks], bh);
        }
        S[jt][0] = acc[0]; S[jt][1] = acc[1];
        S[jt][2] = acc[2]; S[jt][3] = acc[3];
        mx0 = fmaxf(mx0, fmaxf(acc[0], acc[1]));
        mx1 = fmaxf(mx1, fmaxf(acc[2], acc[3]));
    }

    // ---- row max: quad reduce -> smem -> per-thread gather ----
    mx0 = fmaxf(mx0, __shfl_xor_sync(0xffffffffu, mx0, 1));
    mx0 = fmaxf(mx0, __shfl_xor_sync(0xffffffffu, mx0, 2));
    mx1 = fmaxf(mx1, __shfl_xor_sync(0xffffffffu, mx1, 1));
    mx1 = fmaxf(mx1, __shfl_xor_sync(0xffffffffu, mx1, 2));
    if (tg == 0) { red[warp][g] = mx0; red[warp][g + 8] = mx1; }
    __syncthreads();
    float mxA = red[0][g], mxB = red[0][g + 8];
#pragma unroll
    for (int w = 1; w < 16; w++) {
        mxA = fmaxf(mxA, red[w][g]);
        mxB = fmaxf(mxB, red[w][g + 8]);
    }
    const float scA = 1.0f / mxA;   // TEMP = 1
    const float scB = 1.0f / mxB;

    // ---- exp in registers + row sum ----
    float sm0 = 0.f, sm1 = 0.f;
#pragma unroll
    for (int jt = 0; jt < 16; jt++) {
        S[jt][0] = __expf(S[jt][0] * scA);
        S[jt][1] = __expf(S[jt][1] * scA);
        S[jt][2] = __expf(S[jt][2] * scB);
        S[jt][3] = __expf(S[jt][3] * scB);
        sm0 += S[jt][0] + S[jt][1];
        sm1 += S[jt][2] + S[jt][3];
    }
    sm0 += __shfl_xor_sync(0xffffffffu, sm0, 1);
    sm0 += __shfl_xor_sync(0xffffffffu, sm0, 2);
    sm1 += __shfl_xor_sync(0xffffffffu, sm1, 1);
    sm1 += __shfl_xor_sync(0xffffffffu, sm1, 2);
    __syncthreads();           // done reading red (max)
    if (tg == 0) { red[warp][g] = sm0; red[warp][g + 8] = sm1; }
    __syncthreads();
    float suA = 0.f, suB = 0.f;
#pragma unroll
    for (int w = 0; w < 16; w++) {
        suA += red[w][g];
        suB += red[w][g + 8];
    }
    const float invA = 1.0f / suA;
    const float invB = 1.0f / suB;

    // ---- write out directly from registers ----
    float* rowA = out + ((size_t)(b * SEQ + i0 + g)) * SEQ + warp * 8 + 2 * tg;
    float* rowB = out + ((size_t)(b * SEQ + i0 + g + 8)) * SEQ + warp * 8 + 2 * tg;
#pragma unroll
    for (int jt = 0; jt < 16; jt++) {
        *reinterpret_cast<float2*>(rowA + jt * 128) = make_float2(S[jt][0] * invA, S[jt][1] * invA);
        *reinterpret_cast<float2*>(rowB + jt * 128) = make_float2(S[jt][2] * invB, S[jt][3] * invB);
    }
}

// ---------------------------------------------------------------------------
extern "C" void kernel_launch(void* const* d_in, const int* in_sizes, int n_in,
                              void* d_out, int out_size)
{
    const float* x   = (const float*)d_in[0];
    const float* qW1 = (const float*)d_in[1];
    const float* qb1 = (const float*)d_in[2];
    const float* qW2 = (const float*)d_in[3];
    const float* qb2 = (const float*)d_in[4];
    const float* kW1 = (const float*)d_in[5];
    const float* kb1 = (const float*)d_in[6];
    const float* kW2 = (const float*)d_in[7];
    const float* kb2 = (const float*)d_in[8];
    float* out = (float*)d_out;

    cudaFuncSetAttribute(mlp_kernel, cudaFuncAttributeMaxDynamicSharedMemorySize, MLP_SMEM);
    cudaFuncSetAttribute(qks_kernel, cudaFuncAttributeMaxDynamicSharedMemorySize, QKS_SMEM);

    prep_kernel<<<(2 * HID * DIM + 255) / 256, 256>>>(qW1, kW1, qW2, kW2);
    mlp_kernel<<<dim3(512, 2), 256, MLP_SMEM>>>(x, qb1, qb2, kb1, kb2);
    qks_kernel<<<dim3(SEQ / 16, BATCH), 512, QKS_SMEM>>>(out);
}

// round 7
// speedup vs baseline: 2.5505x; 1.0529x over previous
#include <cuda_runtime.h>
#include <cuda_bf16.h>
#include <cstdint>

#define BATCH 16
#define SEQ   2048
#define DIM   128
#define HID   256
#define KOUT  64
#define NROWS (BATCH * SEQ)   // 32768

// ---------------------------------------------------------------------------
// Device scratch: hi/lo bf16 split weights + Q/K projections
// ---------------------------------------------------------------------------
__device__ __nv_bfloat16 g_W1T_hi[2 * HID * DIM], g_W1T_lo[2 * HID * DIM];
__device__ __nv_bfloat16 g_W2T_hi[2 * KOUT * HID], g_W2T_lo[2 * KOUT * HID];
__device__ __nv_bfloat16 g_Qhi[NROWS * KOUT], g_Qlo[NROWS * KOUT];
__device__ __nv_bfloat16 g_Khi[NROWS * KOUT], g_Klo[NROWS * KOUT];

// ---------------------------------------------------------------------------
// Helpers
// ---------------------------------------------------------------------------
__device__ __forceinline__ void mma_bf16(float* c, const uint32_t* a, const uint32_t* b) {
    asm volatile(
        "mma.sync.aligned.m16n8k16.row.col.f32.bf16.bf16.f32 "
        "{%0,%1,%2,%3},{%4,%5,%6,%7},{%8,%9},{%0,%1,%2,%3};\n"
        : "+f"(c[0]), "+f"(c[1]), "+f"(c[2]), "+f"(c[3])
        : "r"(a[0]), "r"(a[1]), "r"(a[2]), "r"(a[3]), "r"(b[0]), "r"(b[1]));
}

#define LDSM_X4(r0, r1, r2, r3, a) \
    asm volatile("ldmatrix.sync.aligned.m8n8.x4.shared.b16 {%0,%1,%2,%3},[%4];" \
                 : "=r"(r0), "=r"(r1), "=r"(r2), "=r"(r3) : "r"(a))

#define CP_ASYNC16(dst, src) \
    asm volatile("cp.async.cg.shared.global [%0],[%1],16;\n" :: "r"(dst), "l"(src))
#define CP_COMMIT() asm volatile("cp.async.commit_group;\n")
#define CP_WAIT0()  asm volatile("cp.async.wait_group 0;\n")
#define CP_WAIT1()  asm volatile("cp.async.wait_group 1;\n")
#define CP_WAIT2()  asm volatile("cp.async.wait_group 2;\n")

__device__ __forceinline__ void split1(float v, __nv_bfloat16& h, __nv_bfloat16& l) {
    h = __float2bfloat16(v);
    l = __float2bfloat16(v - __bfloat162float(h));
}

__device__ __forceinline__ void split_pack(float a, float b, uint32_t& hi, uint32_t& lo) {
    __nv_bfloat16 ha, la, hb, lb;
    split1(a, ha, la);
    split1(b, hb, lb);
    __nv_bfloat162 H = __halves2bfloat162(ha, hb);
    __nv_bfloat162 L = __halves2bfloat162(la, lb);
    hi = *reinterpret_cast<uint32_t*>(&H);
    lo = *reinterpret_cast<uint32_t*>(&L);
}

// ---------------------------------------------------------------------------
// K0: prep — split W1^T, W2^T into hi/lo bf16
// ---------------------------------------------------------------------------
__global__ void __launch_bounds__(256) prep_kernel(
    const float* __restrict__ qW1, const float* __restrict__ kW1,
    const float* __restrict__ qW2, const float* __restrict__ kW2)
{
    int t = blockIdx.x * 256 + threadIdx.x;
    if (t < 2 * HID * DIM) {            // W1^T [head][n=256][k=128]
        int head = t / (HID * DIM);
        int r = t % (HID * DIM);
        int n = r / DIM, k = r % DIM;
        float v = (head ? kW1 : qW1)[k * HID + n];
        __nv_bfloat16 h, l;
        split1(v, h, l);
        g_W1T_hi[t] = h; g_W1T_lo[t] = l;
    }
    if (t < 2 * KOUT * HID) {           // W2^T [head][n=64][k=256]
        int head = t / (KOUT * HID);
        int r = t % (KOUT * HID);
        int n = r / HID, k = r % HID;
        float v = (head ? kW2 : qW2)[k * KOUT + n];
        __nv_bfloat16 h, l;
        split1(v, h, l);
        g_W2T_hi[t] = h; g_W2T_lo[t] = l;
    }
}

// ---------------------------------------------------------------------------
// K1: MLP via bf16x3 mma.sync + ldmatrix.  CTA = 64 rows, one head, 256 thr.
// smem words: XS hi 0 / lo 4352; W1 ring MR(s)=8704+s*8704 (3 stages);
//             HS hi 34816 / lo 43264.  Total 206848 B.
// ---------------------------------------------------------------------------
#define MXS_HI 0
#define MXS_LO 4352
#define MR(s)  (8704 + (s) * 8704)
#define MHS_HI 34816
#define MHS_LO 43264
#define MLP_SMEM 206848

__global__ void __launch_bounds__(256, 1) mlp_kernel(
    const float* __restrict__ x,
    const float* __restrict__ qb1, const float* __restrict__ qb2,
    const float* __restrict__ kb1, const float* __restrict__ kb2)
{
    extern __shared__ uint32_t smw[];
    const uint32_t sbase = (uint32_t)__cvta_generic_to_shared(smw);

    const int tid  = threadIdx.x;
    const int head = blockIdx.y;
    const int m0   = blockIdx.x * 64;
    const float* B1 = head ? kb1 : qb1;
    const float* B2 = head ? kb2 : qb2;

    const int warp = tid >> 5;
    const int lane = tid & 31;
    const int g  = lane >> 2;
    const int tg = lane & 3;

    // ---- issue W1 chunks 0..2 into ring stages 0..2 ----
#pragma unroll
    for (int s = 0; s < 3; s++) {
#pragma unroll
        for (int i = 0; i < 8; i++) {
            int c = tid + 256 * i;
            int ishi = (c < 1024);
            int cc = c & 1023;
            int row = cc >> 4, ch = cc & 15;
            const __nv_bfloat16* src = (ishi ? g_W1T_hi : g_W1T_lo)
                + (size_t)head * HID * DIM + (size_t)(s * 64 + row) * DIM + ch * 8;
            CP_ASYNC16(sbase + MR(s) * 4 + (ishi ? 0 : 17408) + row * 272 + ch * 16, src);
        }
        CP_COMMIT();
    }

    // ---- X: LDG f32, split, STS ----
    {
        int row = tid >> 2;
        int c0  = (tid & 3) * 32;
        const float4* xr = reinterpret_cast<const float4*>(x + (size_t)(m0 + row) * DIM + c0);
#pragma unroll
        for (int i = 0; i < 8; i++) {
            float4 v = xr[i];
            uint32_t h0, l0, h1, l1;
            split_pack(v.x, v.y, h0, l0);
            split_pack(v.z, v.w, h1, l1);
            int wc = (c0 >> 1) + i * 2;
            smw[MXS_HI + row * 68 + wc]     = h0;
            smw[MXS_HI + row * 68 + wc + 1] = h1;
            smw[MXS_LO + row * 68 + wc]     = l0;
            smw[MXS_LO + row * 68 + wc + 1] = l1;
        }
    }

    // ---- GEMM1: 4 n-chunks of 64, ring-3 pipelined ----
    const int wm = warp >> 1;     // 0..3 -> rows wm*16
    const int wn = warp & 1;      // 0..1 -> cols wn*32 (within chunk)
    const int r0 = wm * 16 + g;

    // ldmatrix base addresses (lane-based)
    const uint32_t axh = sbase +
        (uint32_t)((wm * 16 + (lane & 7) + ((lane >> 3) & 1) * 8) * 272 + (lane >> 4) * 16);

#pragma unroll
    for (int nc = 0; nc < 4; nc++) {
        if (nc == 0) CP_WAIT2(); else CP_WAIT1();
        __syncthreads();
        if (nc == 1) {           // W1 chunk 3 -> R0
#pragma unroll
            for (int i = 0; i < 8; i++) {
                int c = tid + 256 * i;
                int ishi = (c < 1024);
                int cc = c & 1023;
                int row = cc >> 4, ch = cc & 15;
                const __nv_bfloat16* src = (ishi ? g_W1T_hi : g_W1T_lo)
                    + (size_t)head * HID * DIM + (size_t)(192 + row) * DIM + ch * 8;
                CP_ASYNC16(sbase + MR(0) * 4 + (ishi ? 0 : 17408) + row * 272 + ch * 16, src);
            }
            CP_COMMIT();
        } else if (nc == 2) {    // W2 hi -> R1
#pragma unroll
            for (int i = 0; i < 8; i++) {
                int c = tid + 256 * i;
                int row = c >> 5, ch = c & 31;
                const __nv_bfloat16* src = g_W2T_hi
                    + (size_t)head * KOUT * HID + (size_t)row * HID + ch * 8;
                CP_ASYNC16(sbase + MR(1) * 4 + row * 528 + ch * 16, src);
            }
            CP_COMMIT();
        } else if (nc == 3) {    // W2 lo -> R2
#pragma unroll
            for (int i = 0; i < 8; i++) {
                int c = tid + 256 * i;
                int row = c >> 5, ch = c & 31;
                const __nv_bfloat16* src = g_W2T_lo
                    + (size_t)head * KOUT * HID + (size_t)row * HID + ch * 8;
                CP_ASYNC16(sbase + MR(2) * 4 + row * 528 + ch * 16, src);
            }
            CP_COMMIT();
        }

        const uint32_t bxr = sbase + (uint32_t)(MR(nc % 3) * 4)
            + (uint32_t)((wn * 32 + (lane & 7)) * 272 + (lane >> 3) * 16);

        float acc[4][4];
#pragma unroll
        for (int nf = 0; nf < 4; nf++) {
            int col = nc * 64 + wn * 32 + nf * 8 + 2 * tg;
            float2 bv = *reinterpret_cast<const float2*>(B1 + col);
            acc[nf][0] = bv.x; acc[nf][1] = bv.y;
            acc[nf][2] = bv.x; acc[nf][3] = bv.y;
        }
#pragma unroll
        for (int p = 0; p < 4; p++) {       // k-step pairs (ks = 2p, 2p+1)
            uint32_t ah0[4], ah1[4], al0[4], al1[4];
            LDSM_X4(ah0[0], ah0[1], ah0[2], ah0[3], axh + (2 * p) * 32);
            LDSM_X4(ah1[0], ah1[1], ah1[2], ah1[3], axh + (2 * p + 1) * 32);
            LDSM_X4(al0[0], al0[1], al0[2], al0[3], axh + 17408 + (2 * p) * 32);
            LDSM_X4(al1[0], al1[1], al1[2], al1[3], axh + 17408 + (2 * p + 1) * 32);
#pragma unroll
            for (int nf = 0; nf < 4; nf++) {
                uint32_t bh[4], bl[4];
                LDSM_X4(bh[0], bh[1], bh[2], bh[3], bxr + nf * 2176 + p * 64);
                LDSM_X4(bl[0], bl[1], bl[2], bl[3], bxr + 17408 + nf * 2176 + p * 64);
                mma_bf16(acc[nf], ah0, bh);     mma_bf16(acc[nf], ah0, bl);
                mma_bf16(acc[nf], al0, bh);
                mma_bf16(acc[nf], ah1, bh + 2); mma_bf16(acc[nf], ah1, bl + 2);
                mma_bf16(acc[nf], al1, bh + 2);
            }
        }
        // epilogue: relu + split -> HS
#pragma unroll
        for (int nf = 0; nf < 4; nf++) {
            int hw = nc * 32 + wn * 16 + nf * 4 + tg;
            uint32_t hi, lo;
            split_pack(fmaxf(acc[nf][0], 0.f), fmaxf(acc[nf][1], 0.f), hi, lo);
            smw[MHS_HI + 132 * r0 + hw] = hi;
            smw[MHS_LO + 132 * r0 + hw] = lo;
            split_pack(fmaxf(acc[nf][2], 0.f), fmaxf(acc[nf][3], 0.f), hi, lo);
            smw[MHS_HI + 132 * (r0 + 8) + hw] = hi;
            smw[MHS_LO + 132 * (r0 + 8) + hw] = lo;
        }
    }

    CP_WAIT0();      // W2 hi+lo landed
    __syncthreads(); // HS complete

    // ---- GEMM2: [64x256] @ W2T^T -> [64x64] ----
    {
        const int wm2 = warp >> 1;
        const int wn2 = warp & 1;
        const int n_off = wn2 * 32;

        const uint32_t ahr = sbase + 139264u +
            (uint32_t)((wm2 * 16 + (lane & 7) + ((lane >> 3) & 1) * 8) * 528 + (lane >> 4) * 16);
        const uint32_t alr = ahr + 33792u;
        const uint32_t bhr = sbase + (uint32_t)(MR(1) * 4)
            + (uint32_t)((n_off + (lane & 7)) * 528 + (lane >> 3) * 16);
        const uint32_t blr = sbase + (uint32_t)(MR(2) * 4)
            + (uint32_t)((n_off + (lane & 7)) * 528 + (lane >> 3) * 16);

        float acc[4][4];
#pragma unroll
        for (int nf = 0; nf < 4; nf++) {
            int col = n_off + nf * 8 + 2 * tg;
            float2 bv = *reinterpret_cast<const float2*>(B2 + col);
            acc[nf][0] = bv.x; acc[nf][1] = bv.y;
            acc[nf][2] = bv.x; acc[nf][3] = bv.y;
        }
#pragma unroll
        for (int p = 0; p < 8; p++) {
            uint32_t ah0[4], ah1[4], al0[4], al1[4];
            LDSM_X4(ah0[0], ah0[1], ah0[2], ah0[3], ahr + (2 * p) * 32);
            LDSM_X4(ah1[0], ah1[1], ah1[2], ah1[3], ahr + (2 * p + 1) * 32);
            LDSM_X4(al0[0], al0[1], al0[2], al0[3], alr + (2 * p) * 32);
            LDSM_X4(al1[0], al1[1], al1[2], al1[3], alr + (2 * p + 1) * 32);
#pragma unroll
            for (int nf = 0; nf < 4; nf++) {
                uint32_t bh[4], bl[4];
                LDSM_X4(bh[0], bh[1], bh[2], bh[3], bhr + nf * 4224 + p * 64);
                LDSM_X4(bl[0], bl[1], bl[2], bl[3], blr + nf * 4224 + p * 64);
                mma_bf16(acc[nf], ah0, bh);     mma_bf16(acc[nf], ah0, bl);
                mma_bf16(acc[nf], al0, bh);
                mma_bf16(acc[nf], ah1, bh + 2); mma_bf16(acc[nf], ah1, bl + 2);
                mma_bf16(acc[nf], al1, bh + 2);
            }
        }
        __nv_bfloat16* Ohi = head ? g_Khi : g_Qhi;
        __nv_bfloat16* Olo = head ? g_Klo : g_Qlo;
#pragma unroll
        for (int nf = 0; nf < 4; nf++) {
            int col = n_off + nf * 8 + 2 * tg;
            int row0 = m0 + wm2 * 16 + g;
            uint32_t hi, lo;
            split_pack(acc[nf][0], acc[nf][1], hi, lo);
            *reinterpret_cast<uint32_t*>(&Ohi[(size_t)row0 * KOUT + col]) = hi;
            *reinterpret_cast<uint32_t*>(&Olo[(size_t)row0 * KOUT + col]) = lo;
            split_pack(acc[nf][2], acc[nf][3], hi, lo);
            *reinterpret_cast<uint32_t*>(&Ohi[(size_t)(row0 + 8) * KOUT + col]) = hi;
            *reinterpret_cast<uint32_t*>(&Olo[(size_t)(row0 + 8) * KOUT + col]) = lo;
        }
    }
}

// ---------------------------------------------------------------------------
// K2: fused QK^T + max-division softmax.  CTA = 16 rows x 2048 cols, 512 thr.
// S in registers; K streamed through 4-stage cp.async ring; ldmatrix frags.
// smem words: Q hi 0 / lo 576; K stage s at 1152+s*9216 (hi, lo +4608)
// ---------------------------------------------------------------------------
#define QKW(s) (1152 + (s) * 9216)
#define QKS_SMEM 152064

__global__ void __launch_bounds__(512, 1) qks_kernel(float* __restrict__ out)
{
    extern __shared__ uint32_t smw[];
    __shared__ float red[16][16];
    const uint32_t sbase = (uint32_t)__cvta_generic_to_shared(smw);

    const int tid  = threadIdx.x;
    const int warp = tid >> 5;
    const int lane = tid & 31;
    const int g  = lane >> 2;
    const int tg = lane & 3;
    const int b  = blockIdx.y;
    const int i0 = blockIdx.x * 16;

#define K_LOAD(slot, jtile)                                                        \
    {                                                                              \
        _Pragma("unroll")                                                          \
        for (int i = 0; i < 4; i++) {                                              \
            int c = tid + 512 * i;                                                 \
            int ishi = (c < 1024);                                                 \
            int cc = c & 1023;                                                     \
            int row = cc >> 3, ch = cc & 7;                                        \
            const __nv_bfloat16* src = (ishi ? g_Khi : g_Klo)                      \
                + ((size_t)(b * SEQ + (jtile) * 128 + row)) * KOUT + ch * 8;       \
            CP_ASYNC16(sbase + QKW(slot) * 4 + (ishi ? 0 : 18432) + row * 144 + ch * 16, src); \
        }                                                                          \
    }

    // group 0: Q + K tile 0
    if (tid < 256) {
        int c = tid;
        int ishi = (c < 128);
        int cc = c & 127;
        int row = cc >> 3, ch = cc & 7;
        const __nv_bfloat16* src = (ishi ? g_Qhi : g_Qlo)
            + ((size_t)(b * SEQ + i0 + row)) * KOUT + ch * 8;
        CP_ASYNC16(sbase + (ishi ? 0 : 2304) + row * 144 + ch * 16, src);
    }
    K_LOAD(0, 0); CP_COMMIT();
    K_LOAD(1, 1); CP_COMMIT();
    K_LOAD(2, 2); CP_COMMIT();

    uint32_t qh[4][4], ql[4][4];
    float S[16][4];
    const float NEG_INF = __int_as_float(0xff800000);
    float mx0 = NEG_INF, mx1 = NEG_INF;

    // lane-based ldmatrix offsets
    const uint32_t qrow = sbase +
        (uint32_t)(((lane & 7) + ((lane >> 3) & 1) * 8) * 144 + (lane >> 4) * 16);
    const uint32_t krow = (uint32_t)((warp * 8 + (lane & 7)) * 144 + (lane >> 3) * 16);

#pragma unroll
    for (int jt = 0; jt < 16; jt++) {
        if (jt <= 13) CP_WAIT2(); else if (jt == 14) CP_WAIT1(); else CP_WAIT0();
        __syncthreads();

        if (jt == 0) {
            // Q fragments (a-frag) via ldmatrix, kept in registers
#pragma unroll
            for (int ks = 0; ks < 4; ks++) {
                LDSM_X4(qh[ks][0], qh[ks][1], qh[ks][2], qh[ks][3], qrow + ks * 32);
                LDSM_X4(ql[ks][0], ql[ks][1], ql[ks][2], ql[ks][3], qrow + 2304 + ks * 32);
            }
        }
        if (jt + 3 <= 15) {
            K_LOAD((jt + 3) & 3, jt + 3);
            CP_COMMIT();
        }

        const uint32_t kbase = sbase + (uint32_t)(QKW(jt & 3) * 4) + krow;
        uint32_t h[8], l[8];
        LDSM_X4(h[0], h[1], h[2], h[3], kbase);
        LDSM_X4(h[4], h[5], h[6], h[7], kbase + 64);
        LDSM_X4(l[0], l[1], l[2], l[3], kbase + 18432);
        LDSM_X4(l[4], l[5], l[6], l[7], kbase + 18432 + 64);

        float acc[4] = {0.f, 0.f, 0.f, 0.f};
#pragma unroll
        for (int ks = 0; ks < 4; ks++) {
            mma_bf16(acc, qh[ks], h + 2 * ks);
            mma_bf16(acc, qh[ks], l + 2 * ks);
            mma_bf16(acc, ql[ks], h + 2 * ks);
        }
        S[jt][0] = acc[0]; S[jt][1] = acc[1];
        S[jt][2] = acc[2]; S[jt][3] = acc[3];
        mx0 = fmaxf(mx0, fmaxf(acc[0], acc[1]));
        mx1 = fmaxf(mx1, fmaxf(acc[2], acc[3]));
    }

    // ---- row max ----
    mx0 = fmaxf(mx0, __shfl_xor_sync(0xffffffffu, mx0, 1));
    mx0 = fmaxf(mx0, __shfl_xor_sync(0xffffffffu, mx0, 2));
    mx1 = fmaxf(mx1, __shfl_xor_sync(0xffffffffu, mx1, 1));
    mx1 = fmaxf(mx1, __shfl_xor_sync(0xffffffffu, mx1, 2));
    if (tg == 0) { red[warp][g] = mx0; red[warp][g + 8] = mx1; }
    __syncthreads();
    float mxA = red[0][g], mxB = red[0][g + 8];
#pragma unroll
    for (int w = 1; w < 16; w++) {
        mxA = fmaxf(mxA, red[w][g]);
        mxB = fmaxf(mxB, red[w][g + 8]);
    }
    const float scA = 1.0f / mxA;   // TEMP = 1
    const float scB = 1.0f / mxB;

    // ---- exp + row sum ----
    float sm0 = 0.f, sm1 = 0.f;
#pragma unroll
    for (int jt = 0; jt < 16; jt++) {
        S[jt][0] = __expf(S[jt][0] * scA);
        S[jt][1] = __expf(S[jt][1] * scA);
        S[jt][2] = __expf(S[jt][2] * scB);
        S[jt][3] = __expf(S[jt][3] * scB);
        sm0 += S[jt][0] + S[jt][1];
        sm1 += S[jt][2] + S[jt][3];
    }
    sm0 += __shfl_xor_sync(0xffffffffu, sm0, 1);
    sm0 += __shfl_xor_sync(0xffffffffu, sm0, 2);
    sm1 += __shfl_xor_sync(0xffffffffu, sm1, 1);
    sm1 += __shfl_xor_sync(0xffffffffu, sm1, 2);
    __syncthreads();
    if (tg == 0) { red[warp][g] = sm0; red[warp][g + 8] = sm1; }
    __syncthreads();
    float suA = 0.f, suB = 0.f;
#pragma unroll
    for (int w = 0; w < 16; w++) {
        suA += red[w][g];
        suB += red[w][g + 8];
    }
    const float invA = 1.0f / suA;
    const float invB = 1.0f / suB;

    // ---- write out ----
    float* rowA = out + ((size_t)(b * SEQ + i0 + g)) * SEQ + warp * 8 + 2 * tg;
    float* rowB = out + ((size_t)(b * SEQ + i0 + g + 8)) * SEQ + warp * 8 + 2 * tg;
#pragma unroll
    for (int jt = 0; jt < 16; jt++) {
        *reinterpret_cast<float2*>(rowA + jt * 128) = make_float2(S[jt][0] * invA, S[jt][1] * invA);
        *reinterpret_cast<float2*>(rowB + jt * 128) = make_float2(S[jt][2] * invB, S[jt][3] * invB);
    }
}

// ---------------------------------------------------------------------------
extern "C" void kernel_launch(void* const* d_in, const int* in_sizes, int n_in,
                              void* d_out, int out_size)
{
    const float* x   = (const float*)d_in[0];
    const float* qW1 = (const float*)d_in[1];
    const float* qb1 = (const float*)d_in[2];
    const float* qW2 = (const float*)d_in[3];
    const float* qb2 = (const float*)d_in[4];
    const float* kW1 = (const float*)d_in[5];
    const float* kb1 = (const float*)d_in[6];
    const float* kW2 = (const float*)d_in[7];
    const float* kb2 = (const float*)d_in[8];
    float* out = (float*)d_out;

    cudaFuncSetAttribute(mlp_kernel, cudaFuncAttributeMaxDynamicSharedMemorySize, MLP_SMEM);
    cudaFuncSetAttribute(qks_kernel, cudaFuncAttributeMaxDynamicSharedMemorySize, QKS_SMEM);

    prep_kernel<<<(2 * HID * DIM + 255) / 256, 256>>>(qW1, kW1, qW2, kW2);
    mlp_kernel<<<dim3(512, 2), 256, MLP_SMEM>>>(x, qb1, qb2, kb1, kb2);
    qks_kernel<<<dim3(SEQ / 16, BATCH), 512, QKS_SMEM>>>(out);
}